// round 5
// baseline (speedup 1.0000x reference)
#include <cuda_runtime.h>
#include <cstdint>

// RBM block-Gibbs chain, fused single kernel.
// Each sample's 30-step chain is independent -> run it entirely in registers.
// PRNG replicates JAX threefry2x32 with jax_threefry_partitionable=True.

#define NSAMP   524288
#define LATENT  128
#define NSTEPS  30
#define GPW     4                 // samples per warp
#define WARPS_PB 8
#define THREADS_PB (WARPS_PB * 32)
#define NBLOCKS (NSAMP / (GPW * WARPS_PB))   // 16384

struct Keys { uint2 k[1 + NSTEPS]; };  // k[0] = z0 key, k[1+t] = step t key

__host__ __device__ __forceinline__ uint32_t rotl32(uint32_t x, int r) {
#ifdef __CUDA_ARCH__
    return __funnelshift_l(x, x, r);
#else
    return (x << r) | (x >> (32 - r));
#endif
}

// Threefry-2x32, 20 rounds (exactly JAX's threefry2x32).
__host__ __device__ __forceinline__ uint2 tf2x32(uint32_t k0, uint32_t k1,
                                                 uint32_t x0, uint32_t x1) {
    uint32_t k2 = k0 ^ k1 ^ 0x1BD11BDAu;
    x0 += k0; x1 += k1;
#define TFR(r) { x0 += x1; x1 = rotl32(x1, r); x1 ^= x0; }
    TFR(13) TFR(15) TFR(26) TFR(6)   x0 += k1; x1 += k2 + 1u;
    TFR(17) TFR(29) TFR(16) TFR(24)  x0 += k2; x1 += k0 + 2u;
    TFR(13) TFR(15) TFR(26) TFR(6)   x0 += k0; x1 += k1 + 3u;
    TFR(17) TFR(29) TFR(16) TFR(24)  x0 += k1; x1 += k2 + 4u;
    TFR(13) TFR(15) TFR(26) TFR(6)   x0 += k2; x1 += k0 + 5u;
#undef TFR
    return make_uint2(x0, x1);
}

// Partitionable-mode random bits: counter = (hi=0, lo=flat_index), xor both lanes.
__device__ __forceinline__ uint32_t tf_bits(uint32_t k0, uint32_t k1, uint32_t ctr) {
    uint2 r = tf2x32(k0, k1, 0u, ctr);
    return r.x ^ r.y;
}

__global__ __launch_bounds__(THREADS_PB)
void rbm_gibbs_kernel(const float* __restrict__ hvec,
                      const float* __restrict__ W,
                      float* __restrict__ out,
                      Keys keys) {
    const int lane = threadIdx.x & 31;
    const int warp = threadIdx.x >> 5;
    const int wglob = blockIdx.x * WARPS_PB + warp;
    const int s0 = wglob * GPW;                 // first sample of this warp

    const float4* __restrict__ W4 = reinterpret_cast<const float4*>(W);
    const float4 h4 = reinterpret_cast<const float4*>(hvec)[lane];

    // z as floats {0,1}: zq[g][c] holds z for sample s0+g, dim = lane*4+c
    float zq[GPW][4];

    // ---- init z0 = randint(k_init, ..., 0, 2) = bits & 1 ----
    {
        const uint32_t ik0 = keys.k[0].x, ik1 = keys.k[0].y;
#pragma unroll
        for (int g = 0; g < GPW; g++) {
            uint32_t base = (uint32_t)(s0 + g) * (uint32_t)LATENT + (uint32_t)(lane * 4);
#pragma unroll
            for (int c = 0; c < 4; c++) {
                uint32_t b = tf_bits(ik0, ik1, base + (uint32_t)c);
                zq[g][c] = (float)(b & 1u);
            }
        }
    }

    // ---- 30 Gibbs steps ----
    for (int t = 0; t < NSTEPS; t++) {
        const uint2 sk = keys.k[1 + t];

        float y[GPW][4];
#pragma unroll
        for (int g = 0; g < GPW; g++) {
            y[g][0] = h4.x; y[g][1] = h4.y; y[g][2] = h4.z; y[g][3] = h4.w;
        }

        // y += z @ W : dim k = 4*k0 + c lives at lane k0, register component c.
        for (int k0 = 0; k0 < 32; k0++) {
#pragma unroll
            for (int c = 0; c < 4; c++) {
                const int k = k0 * 4 + c;
                float4 w = __ldg(&W4[k * 32 + lane]);   // W[k][lane*4 .. +3]
#pragma unroll
                for (int g = 0; g < GPW; g++) {
                    float zk = __shfl_sync(0xffffffffu, zq[g][c], k0);
                    y[g][0] += zk * w.x;
                    y[g][1] += zk * w.y;
                    y[g][2] += zk * w.z;
                    y[g][3] += zk * w.w;
                }
            }
        }

        // sample: u = uniform(step_key), z' = (u < sigmoid(y))
#pragma unroll
        for (int g = 0; g < GPW; g++) {
            uint32_t base = (uint32_t)(s0 + g) * (uint32_t)LATENT + (uint32_t)(lane * 4);
#pragma unroll
            for (int c = 0; c < 4; c++) {
                uint32_t b = tf_bits(sk.x, sk.y, base + (uint32_t)c);
                float u = __uint_as_float((b >> 9) | 0x3f800000u) - 1.0f;
                float p = 1.0f / (1.0f + expf(-y[g][c]));
                zq[g][c] = (u < p) ? 1.0f : 0.0f;
            }
        }
    }

    // ---- write z_final (float32, row-major [NSAMP, 128]) ----
#pragma unroll
    for (int g = 0; g < GPW; g++) {
        float4 v = make_float4(zq[g][0], zq[g][1], zq[g][2], zq[g][3]);
        reinterpret_cast<float4*>(out)[((size_t)(s0 + g) * LATENT + lane * 4) >> 2] = v;
    }
}

extern "C" void kernel_launch(void* const* d_in, const int* in_sizes, int n_in,
                              void* d_out, int out_size) {
    (void)in_sizes; (void)n_in; (void)out_size;
    const float* h = (const float*)d_in[0];
    const float* W = (const float*)d_in[1];
    float* out = (float*)d_out;

    // Host-side key schedule (pure CPU math; deterministic, capture-safe).
    // key(42) -> data (0, 42); partitionable fold-like split:
    //   k_init = TF(key, 0, 0), k_loop = TF(key, 0, 1), step[t] = TF(k_loop, 0, t)
    Keys keys;
    uint2 kinit = tf2x32(0u, 42u, 0u, 0u);
    uint2 kloop = tf2x32(0u, 42u, 0u, 1u);
    keys.k[0] = kinit;
    for (int t = 0; t < NSTEPS; t++)
        keys.k[1 + t] = tf2x32(kloop.x, kloop.y, 0u, (uint32_t)t);

    rbm_gibbs_kernel<<<NBLOCKS, THREADS_PB>>>(h, W, out, keys);
}